// round 17
// baseline (speedup 1.0000x reference)
#include <cuda_runtime.h>
#include <cuda_fp16.h>

#define NN      100000
#define NE      1600000
#define NG      1024
#define EMB_D   32
#define HID_D   64
#define NC      10
#define NSH     17          // N_SHAPE+1
#define NCO     9           // N_COLOR+1
#define CAP     64          // bucket capacity (deg ~ Poisson(16); max ~50)

// ---------------- scratch (device globals) ----------------------------------
__device__ __half g_hh1[NN * HID_D];  // hs1 = h*dis (fp16, row = 16 uint2)
__device__ __half g_hh2[NN * HID_D];  // hs2 (fp16)
__device__ __half g_ya [NN * HID_D];  // relu'd layer-1 output (fp16, mm2 input)
__device__ float  g_dis[NN];
__device__ int    g_ccnt[NN];         // in-degree / bucket counters
__device__ int    g_bkt [NN * CAP];   // incoming src ids per node (256B rows)
__device__ float  g_st1[NSH * HID_D];
__device__ float  g_ct1[NCO * HID_D];
__device__ float  g_pool[NG * HID_D];
__device__ float  g_cnt[NG];

__device__ __forceinline__ void red_v4(float* p, float4 v) {
    asm volatile("red.global.add.v4.f32 [%0], {%1,%2,%3,%4};"
                 :: "l"(p), "f"(v.x), "f"(v.y), "f"(v.z), "f"(v.w) : "memory");
}

// ---- fp16 pair helpers -------------------------------------------------------
__device__ __forceinline__ void h2add(uint2& a, uint2 b) {
    __half2* pa = (__half2*)&a;
    const __half2* pb = (const __half2*)&b;
    pa[0] = __hadd2(pa[0], pb[0]);
    pa[1] = __hadd2(pa[1], pb[1]);
}
__device__ __forceinline__ void accf(float4& acc, uint2 u) {
    float2 f0 = __half22float2(((const __half2*)&u)[0]);
    float2 f1 = __half22float2(((const __half2*)&u)[1]);
    acc.x += f0.x; acc.y += f0.y; acc.z += f1.x; acc.w += f1.y;
}
__device__ __forceinline__ uint2 pack_h4(float a, float b, float c, float d) {
    uint2 o;
    ((__half2*)&o)[0] = __floats2half2_rn(a, b);
    ((__half2*)&o)[1] = __floats2half2_rn(c, d);
    return o;
}
__device__ __forceinline__ float4 u2_to_f4ull(const ulonglong2& a) {
    float4 r;
    asm("mov.b64 {%0, %1}, %2;" : "=f"(r.x), "=f"(r.y) : "l"(a.x));
    asm("mov.b64 {%0, %1}, %2;" : "=f"(r.z), "=f"(r.w) : "l"(a.y));
    return r;
}
__device__ __forceinline__ unsigned long long packpair(float x) {
    unsigned long long r;
    asm("mov.b64 %0, {%1, %1};" : "=l"(r) : "f"(x));
    return r;
}

// ---------------- bucket build ------------------------------------------------
__global__ void k_fillb(const int* __restrict__ src, const int* __restrict__ dst) {
    int e = blockIdx.x * blockDim.x + threadIdx.x;
    if (e >= NE) return;
    int d = dst[e];
    int p = atomicAdd(&g_ccnt[d], 1);
    if (p < CAP) g_bkt[d * CAP + p] = src[e];
}

// ---------------- layer-1 tables ---------------------------------------------
__global__ void k_tab1(const float* __restrict__ stab, const float* __restrict__ ctab,
                       const float* __restrict__ W1) {
    __shared__ float sW[EMB_D * HID_D];
    for (int t = threadIdx.x; t < EMB_D * HID_D; t += blockDim.x) sW[t] = W1[t];
    __syncthreads();
    for (int idx = threadIdx.x; idx < (NSH + NCO) * HID_D; idx += blockDim.x) {
        int row = idx / HID_D, j = idx % HID_D;
        const float* tab;
        float* out;
        int r;
        if (row < NSH) { tab = stab; out = g_st1; r = row; }
        else           { tab = ctab; out = g_ct1; r = row - NSH; }
        float s = 0.0f;
        if (r != 0) {
#pragma unroll
            for (int k = 0; k < EMB_D; k++)
                s = fmaf(tab[r * EMB_D + k], sW[k * HID_D + j], s);
        }
        out[r * HID_D + j] = s;
    }
}

// hs1 = (ST1[sid]+CT1[cid]) * dis -> g_hh1 (fp16); also dis + pool counts
__global__ void k_hs1(const int* __restrict__ sid, const int* __restrict__ cid,
                      const int* __restrict__ batch) {
    int t = blockIdx.x * blockDim.x + threadIdx.x;
    if (t >= NN * 16) return;
    int i = t >> 4, jq = t & 15;
    float d = rsqrtf(1.0f + (float)__ldg(g_ccnt + i));
    if (jq == 0) {
        g_dis[i] = d;
        atomicAdd(&g_cnt[__ldg(batch + i)], 1.0f);
    }
    int s = __ldg(sid + i), c = __ldg(cid + i);
    float4 sv = ((const float4*)g_st1)[s * 16 + jq];
    float4 cv = ((const float4*)g_ct1)[c * 16 + jq];
    ((uint2*)g_hh1)[t] = pack_h4((sv.x + cv.x) * d, (sv.y + cv.y) * d,
                                 (sv.z + cv.z) * d, (sv.w + cv.w) * d);
}

// ---------------- fp16 bucket gather: pipelined index prefetch ---------------
__device__ __forceinline__ float4 gather_acc_h(const __half* __restrict__ Hb,
                                               int i, int jq) {
    const uint2* H = (const uint2*)Hb;     // row = 16 uint2 (128B)
    int deg = min(__ldg(g_ccnt + i), CAP);
    const int* lst = g_bkt + (long)i * CAP;
    float4 acc = make_float4(0, 0, 0, 0);
    accf(acc, H[i * 16 + jq]);             // self-loop seed
    int e = 0;
    if (e + 8 <= deg) {
        // prefetch first index batch
        int4 sa = __ldg((const int4*)(lst));
        int4 sb = __ldg((const int4*)(lst + 4));
        while (true) {
            // prefetch next index batch BEFORE consuming rows (breaks the
            // idx->row dependency chain across iterations)
            int e2 = e + 8;
            int4 na = sa, nb = sb;
            if (e2 + 8 <= deg) {
                na = __ldg((const int4*)(lst + e2));
                nb = __ldg((const int4*)(lst + e2 + 4));
            }
            uint2 u[8];
            u[0] = H[sa.x * 16 + jq];
            u[1] = H[sa.y * 16 + jq];
            u[2] = H[sa.z * 16 + jq];
            u[3] = H[sa.w * 16 + jq];
            u[4] = H[sb.x * 16 + jq];
            u[5] = H[sb.y * 16 + jq];
            u[6] = H[sb.z * 16 + jq];
            u[7] = H[sb.w * 16 + jq];
            h2add(u[0], u[1]); h2add(u[2], u[3]);
            h2add(u[4], u[5]); h2add(u[6], u[7]);
            h2add(u[0], u[2]); h2add(u[4], u[6]);
            h2add(u[0], u[4]);
            accf(acc, u[0]);
            e = e2;
            if (e + 8 > deg) break;
            sa = na; sb = nb;
        }
    }
    if (e + 4 <= deg) {
        int4 sa = __ldg((const int4*)(lst + e));
        uint2 u0 = H[sa.x * 16 + jq];
        uint2 u1 = H[sa.y * 16 + jq];
        uint2 u2 = H[sa.z * 16 + jq];
        uint2 u3 = H[sa.w * 16 + jq];
        h2add(u0, u1); h2add(u2, u3); h2add(u0, u2);
        accf(acc, u0);
        e += 4;
    }
    for (; e < deg; e++) {
        int s = __ldg(lst + e);
        accf(acc, H[s * 16 + jq]);
    }
    return acc;
}

// layer-1 gather: g_ya = relu(dis * (seed + sum) + b1)  (fp16 out for mm2)
__global__ void k_gather1(const float* __restrict__ bias) {
    int t = blockIdx.x * blockDim.x + threadIdx.x;
    if (t >= NN * 16) return;
    int i = t >> 4, jq = t & 15;
    float4 acc = gather_acc_h(g_hh1, i, jq);
    float d = g_dis[i];
    float4 b = ((const float4*)bias)[jq];
    float4 v;
    v.x = fmaxf(fmaf(d, acc.x, b.x), 0.0f);
    v.y = fmaxf(fmaf(d, acc.y, b.y), 0.0f);
    v.z = fmaxf(fmaf(d, acc.z, b.z), 0.0f);
    v.w = fmaxf(fmaf(d, acc.w, b.w), 0.0f);
    ((uint2*)g_ya)[t] = pack_h4(v.x, v.y, v.z, v.w);
}

// ---------------- mm2: one node per lane, warp-uniform weight reads ----------
__global__ void __launch_bounds__(128)
k_mm2(const float* __restrict__ W2) {
    __shared__ float4 sW[HID_D * 16];     // [k][jq], 16KB
    __shared__ float  sx[128 * 65];       // padded rows (bank-safe)
    int tid = threadIdx.x;
    int node0 = blockIdx.x * 128;

#pragma unroll
    for (int t = tid; t < HID_D * 16; t += 128) sW[t] = ((const float4*)W2)[t];
    // stage fp16 rows -> fp32 padded smem rows
    for (int t = tid; t < 128 * 16; t += 128) {
        int n = t >> 4, q = t & 15;
        int node = node0 + n;
        float4 v = make_float4(0, 0, 0, 0);
        if (node < NN) {
            uint2 u = ((const uint2*)g_ya)[node * 16 + q];
            float2 f0 = __half22float2(((const __half2*)&u)[0]);
            float2 f1 = __half22float2(((const __half2*)&u)[1]);
            v = make_float4(f0.x, f0.y, f1.x, f1.y);
        }
        float* row = sx + n * 65 + q * 4;
        row[0] = v.x; row[1] = v.y; row[2] = v.z; row[3] = v.w;
    }
    __syncthreads();

    int node = node0 + tid;
    if (node >= NN) return;
    float d = g_dis[node];
    const float* xr = sx + tid * 65;
    const ulonglong2* sWp = (const ulonglong2*)sW;

#pragma unroll
    for (int cg = 0; cg < 4; cg++) {
        unsigned long long o[8] = {0, 0, 0, 0, 0, 0, 0, 0};
#pragma unroll 8
        for (int k = 0; k < HID_D; k++) {
            unsigned long long xx = packpair(xr[k]);
#pragma unroll
            for (int q = 0; q < 4; q++) {
                ulonglong2 w = sWp[k * 16 + cg * 4 + q];
                asm("fma.rn.f32x2 %0, %1, %2, %0;" : "+l"(o[2*q])   : "l"(xx), "l"(w.x));
                asm("fma.rn.f32x2 %0, %1, %2, %0;" : "+l"(o[2*q+1]) : "l"(xx), "l"(w.y));
            }
        }
#pragma unroll
        for (int q = 0; q < 4; q++) {
            ulonglong2 t2;
            t2.x = o[2*q]; t2.y = o[2*q+1];
            float4 f = u2_to_f4ull(t2);
            ((uint2*)g_hh2)[node * 16 + cg * 4 + q] =
                pack_h4(f.x * d, f.y * d, f.z * d, f.w * d);
        }
    }
}

// layer-2 gather (reads fp16 g_hh2), epilogue reduces straight into pool
__global__ void k_gather2(const float* __restrict__ bias, const int* __restrict__ batch) {
    int t = blockIdx.x * blockDim.x + threadIdx.x;
    if (t >= NN * 16) return;
    int i = t >> 4, jq = t & 15;
    float4 acc = gather_acc_h(g_hh2, i, jq);
    float d = g_dis[i];
    float4 b = ((const float4*)bias)[jq];
    float4 v;
    v.x = fmaxf(fmaf(d, acc.x, b.x), 0.0f);
    v.y = fmaxf(fmaf(d, acc.y, b.y), 0.0f);
    v.z = fmaxf(fmaf(d, acc.z, b.z), 0.0f);
    v.w = fmaxf(fmaf(d, acc.w, b.w), 0.0f);
    int bt = __ldg(batch + i);
    red_v4(g_pool + bt * HID_D + jq * 4, v);
}

__global__ void k_final(const float* __restrict__ Wl, const float* __restrict__ bl,
                        float* __restrict__ out) {
    int idx = blockIdx.x * blockDim.x + threadIdx.x;
    if (idx >= NG * NC) return;
    int b = idx / NC, c = idx % NC;
    float inv = 1.0f / fmaxf(g_cnt[b], 1.0f);
    float s = bl[c];
#pragma unroll
    for (int j = 0; j < HID_D; j++)
        s = fmaf(g_pool[b * HID_D + j] * inv, Wl[j * NC + c], s);
    out[idx] = s;
}

// ---------------- launch (sequential, single stream) --------------------------
extern "C" void kernel_launch(void* const* d_in, const int* in_sizes, int n_in,
                              void* d_out, int out_size) {
    const int*   shape_id = (const int*)  d_in[0];
    const int*   color_id = (const int*)  d_in[1];
    const int*   edge     = (const int*)  d_in[2];
    const int*   batch    = (const int*)  d_in[3];
    const float* stab     = (const float*)d_in[4];
    const float* ctab     = (const float*)d_in[5];
    const float* W1       = (const float*)d_in[6];
    const float* b1       = (const float*)d_in[7];
    const float* W2       = (const float*)d_in[8];
    const float* b2       = (const float*)d_in[9];
    const float* Wl       = (const float*)d_in[10];
    const float* bl       = (const float*)d_in[11];
    float*       out      = (float*)d_out;

    const int* src = edge;
    const int* dst = edge + NE;

    const int T = 256;
    auto blk = [](long n, int t) { return (int)((n + t - 1) / t); };

    // zero via memset (capture-legal)
    void* p_ccnt = nullptr; cudaGetSymbolAddress(&p_ccnt, g_ccnt);
    void* p_pool = nullptr; cudaGetSymbolAddress(&p_pool, g_pool);
    void* p_cnt  = nullptr; cudaGetSymbolAddress(&p_cnt,  g_cnt);
    cudaMemsetAsync(p_ccnt, 0, NN * sizeof(int), 0);
    cudaMemsetAsync(p_pool, 0, NG * HID_D * sizeof(float), 0);
    cudaMemsetAsync(p_cnt,  0, NG * sizeof(float), 0);

    k_tab1 <<<1, 256>>>(stab, ctab, W1);
    k_fillb<<<blk(NE, T), T>>>(src, dst);

    // layer 1
    k_hs1    <<<blk((long)NN * 16, T), T>>>(shape_id, color_id, batch);
    k_gather1<<<blk((long)NN * 16, T), T>>>(b1);

    // layer 2
    k_mm2    <<<blk(NN, 128), 128>>>(W2);
    k_gather2<<<blk((long)NN * 16, T), T>>>(b2, batch);

    k_final<<<blk(NG * NC, T), T>>>(Wl, bl, out);
}